// round 1
// baseline (speedup 1.0000x reference)
#include <cuda_runtime.h>

// Problem constants
#define BB   8192
#define IN   1024
#define OUTD 256
#define NE   16
#define HH   512
#define TOPK 3

// ---------------- device scratch (statics: allowed; no runtime allocs) ----------------
__device__ int   g_count[NE];                      // tokens routed to each expert
__device__ float g_importance[NE];                 // sum of gates per expert
__device__ int   g_rows[NE * BB];                  // per-expert token row lists (capacity B each)
__device__ int   g_slot[BB * TOPK];                // (row,k) -> slot id (e*BB + pos)
__device__ float g_gate[BB * TOPK];                // (row,k) -> gate value
__device__ float g_h [(size_t)NE * BB * HH];       // hidden activations per slot   (256 MB)
__device__ float g_eo[(size_t)NE * BB * OUTD];     // expert outputs per slot       (128 MB)

// ---------------- kernels ----------------

__global__ void zero_kernel() {
    int t = threadIdx.x;
    if (t < NE) { g_count[t] = 0; g_importance[t] = 0.f; }
}

// One warp per row: logits = x[row] @ w_gate, top-3, softmax, routing.
__global__ void gate_kernel(const float* __restrict__ x, const float* __restrict__ wg) {
    const int warp = threadIdx.x >> 5;
    const int lane = threadIdx.x & 31;
    const int row  = blockIdx.x * 8 + warp;

    const float* xr = x + (size_t)row * IN;
    float acc[NE];
#pragma unroll
    for (int e = 0; e < NE; e++) acc[e] = 0.f;

    for (int i = lane; i < IN; i += 32) {
        float xv = __ldg(xr + i);
        const float* wr = wg + i * NE;
#pragma unroll
        for (int e = 0; e < NE; e++) acc[e] += xv * __ldg(wr + e);
    }
#pragma unroll
    for (int e = 0; e < NE; e++) {
#pragma unroll
        for (int off = 16; off > 0; off >>= 1)
            acc[e] += __shfl_xor_sync(0xffffffffu, acc[e], off);
    }

    if (lane == 0) {
        float l[TOPK]; int ix[TOPK];
#pragma unroll
        for (int k = 0; k < TOPK; k++) {
            float best = -1e30f; int bi = 0;
#pragma unroll
            for (int e = 0; e < NE; e++)
                if (acc[e] > best) { best = acc[e]; bi = e; }
            l[k] = best; ix[k] = bi; acc[bi] = -1e30f;
        }
        // softmax over the 3 selected logits (l[0] is the max)
        float g[TOPK]; float s = 0.f;
#pragma unroll
        for (int k = 0; k < TOPK; k++) { g[k] = expf(l[k] - l[0]); s += g[k]; }
        float inv = 1.f / s;
#pragma unroll
        for (int k = 0; k < TOPK; k++) {
            float gk = g[k] * inv;
            int e = ix[k];
            int pos = atomicAdd(&g_count[e], 1);
            g_rows[e * BB + pos]     = row;
            g_slot[row * TOPK + k]   = e * BB + pos;
            g_gate[row * TOPK + k]   = gk;
            atomicAdd(&g_importance[e], gk);
        }
    }
}

// Single-thread loss: cv^2(importance) + cv^2(load), unbiased var (ddof=1), two-pass.
__global__ void loss_kernel(float* __restrict__ out) {
    float imp[NE], ld[NE];
    float si = 0.f, sl = 0.f;
    for (int e = 0; e < NE; e++) {
        imp[e] = g_importance[e]; ld[e] = (float)g_count[e];
        si += imp[e]; sl += ld[e];
    }
    float mi = si / NE, ml = sl / NE;
    float vi = 0.f, vl = 0.f;
    for (int e = 0; e < NE; e++) {
        float di = imp[e] - mi; vi += di * di;
        float dl = ld[e]  - ml; vl += dl * dl;
    }
    vi /= (NE - 1); vl /= (NE - 1);
    out[0] = vi / (mi * mi + 1e-10f) + vl / (ml * ml + 1e-10f);
}

// Grouped GEMM1 with row gather: H[slot, :] = relu(x[row] @ W1[e] + b1[e])
// Tiles: 128(M) x 128(N) x 16(K), 256 threads, 8x8 microtile per thread.
__global__ __launch_bounds__(256)
void gemm1_kernel(const float* __restrict__ x, const float* __restrict__ W1,
                  const float* __restrict__ b1) {
    const int e  = blockIdx.z;
    const int ne = g_count[e];
    const int m0 = blockIdx.y * 128;
    if (m0 >= ne) return;
    const int n0 = blockIdx.x * 128;

    __shared__ float As[16][128];
    __shared__ float Bs[16][128];

    const int tid = threadIdx.x;
    const int* rows = g_rows + e * BB;
    const float* W1e = W1 + (size_t)e * IN * HH;

    // Precompute gathered A pointers for this thread's two float4 loads.
    const float* aptr[2];
#pragma unroll
    for (int it = 0; it < 2; it++) {
        int idx = tid + it * 256;          // 0..511 float4 slots (128 rows x 4 quads)
        int m   = idx >> 2;
        int kq  = (idx & 3) << 2;
        int mm  = m0 + m;
        int r   = rows[mm < ne ? mm : 0];  // clamp: padding rows compute garbage, never read
        aptr[it] = x + (size_t)r * IN + kq;
    }

    float acc[8][8];
#pragma unroll
    for (int i = 0; i < 8; i++)
#pragma unroll
        for (int j = 0; j < 8; j++) acc[i][j] = 0.f;

    const int ty = tid >> 4, tx = tid & 15;

    for (int k0 = 0; k0 < IN; k0 += 16) {
#pragma unroll
        for (int it = 0; it < 2; it++) {
            int idx = tid + it * 256;
            int m   = idx >> 2;
            int kq  = (idx & 3) << 2;
            float4 v = *(const float4*)(aptr[it] + k0);
            As[kq + 0][m] = v.x; As[kq + 1][m] = v.y;
            As[kq + 2][m] = v.z; As[kq + 3][m] = v.w;
        }
#pragma unroll
        for (int it = 0; it < 2; it++) {
            int idx = tid + it * 256;      // 16 rows x 32 float4
            int kk  = idx >> 5;
            int nq  = (idx & 31) << 2;
            *(float4*)&Bs[kk][nq] = *(const float4*)(W1e + (size_t)(k0 + kk) * HH + n0 + nq);
        }
        __syncthreads();
#pragma unroll
        for (int kk = 0; kk < 16; kk++) {
            float a[8], b[8];
            *(float4*)&a[0] = *(const float4*)&As[kk][ty * 8];
            *(float4*)&a[4] = *(const float4*)&As[kk][ty * 8 + 4];
            *(float4*)&b[0] = *(const float4*)&Bs[kk][tx * 8];
            *(float4*)&b[4] = *(const float4*)&Bs[kk][tx * 8 + 4];
#pragma unroll
            for (int i = 0; i < 8; i++)
#pragma unroll
                for (int j = 0; j < 8; j++) acc[i][j] += a[i] * b[j];
        }
        __syncthreads();
    }

    const float* b1e = b1 + e * HH;
#pragma unroll
    for (int i = 0; i < 8; i++) {
        int m = m0 + ty * 8 + i;
        float* hp = g_h + (size_t)(e * BB + m) * HH + n0 + tx * 8;
#pragma unroll
        for (int j = 0; j < 8; j += 4) {
            float4 v;
            v.x = fmaxf(acc[i][j + 0] + b1e[n0 + tx * 8 + j + 0], 0.f);
            v.y = fmaxf(acc[i][j + 1] + b1e[n0 + tx * 8 + j + 1], 0.f);
            v.z = fmaxf(acc[i][j + 2] + b1e[n0 + tx * 8 + j + 2], 0.f);
            v.w = fmaxf(acc[i][j + 3] + b1e[n0 + tx * 8 + j + 3], 0.f);
            *(float4*)(hp + j) = v;
        }
    }
}

// Grouped GEMM2: EO[slot, :] = H[slot, :] @ W2[e] + b2[e]
__global__ __launch_bounds__(256)
void gemm2_kernel(const float* __restrict__ W2, const float* __restrict__ b2) {
    const int e  = blockIdx.z;
    const int ne = g_count[e];
    const int m0 = blockIdx.y * 128;
    if (m0 >= ne) return;
    const int n0 = blockIdx.x * 128;

    __shared__ float As[16][128];
    __shared__ float Bs[16][128];

    const int tid = threadIdx.x;
    const float* W2e = W2 + (size_t)e * HH * OUTD;

    const float* aptr[2];
#pragma unroll
    for (int it = 0; it < 2; it++) {
        int idx = tid + it * 256;
        int m   = idx >> 2;
        int kq  = (idx & 3) << 2;
        aptr[it] = g_h + (size_t)(e * BB + m0 + m) * HH + kq;
    }

    float acc[8][8];
#pragma unroll
    for (int i = 0; i < 8; i++)
#pragma unroll
        for (int j = 0; j < 8; j++) acc[i][j] = 0.f;

    const int ty = tid >> 4, tx = tid & 15;

    for (int k0 = 0; k0 < HH; k0 += 16) {
#pragma unroll
        for (int it = 0; it < 2; it++) {
            int idx = tid + it * 256;
            int m   = idx >> 2;
            int kq  = (idx & 3) << 2;
            float4 v = *(const float4*)(aptr[it] + k0);
            As[kq + 0][m] = v.x; As[kq + 1][m] = v.y;
            As[kq + 2][m] = v.z; As[kq + 3][m] = v.w;
        }
#pragma unroll
        for (int it = 0; it < 2; it++) {
            int idx = tid + it * 256;
            int kk  = idx >> 5;
            int nq  = (idx & 31) << 2;
            *(float4*)&Bs[kk][nq] = *(const float4*)(W2e + (size_t)(k0 + kk) * OUTD + n0 + nq);
        }
        __syncthreads();
#pragma unroll
        for (int kk = 0; kk < 16; kk++) {
            float a[8], b[8];
            *(float4*)&a[0] = *(const float4*)&As[kk][ty * 8];
            *(float4*)&a[4] = *(const float4*)&As[kk][ty * 8 + 4];
            *(float4*)&b[0] = *(const float4*)&Bs[kk][tx * 8];
            *(float4*)&b[4] = *(const float4*)&Bs[kk][tx * 8 + 4];
#pragma unroll
            for (int i = 0; i < 8; i++)
#pragma unroll
                for (int j = 0; j < 8; j++) acc[i][j] += a[i] * b[j];
        }
        __syncthreads();
    }

    const float* b2e = b2 + e * OUTD;
#pragma unroll
    for (int i = 0; i < 8; i++) {
        int m = m0 + ty * 8 + i;
        float* op = g_eo + (size_t)(e * BB + m) * OUTD + n0 + tx * 8;
#pragma unroll
        for (int j = 0; j < 8; j += 4) {
            float4 v;
            v.x = acc[i][j + 0] + b2e[n0 + tx * 8 + j + 0];
            v.y = acc[i][j + 1] + b2e[n0 + tx * 8 + j + 1];
            v.z = acc[i][j + 2] + b2e[n0 + tx * 8 + j + 2];
            v.w = acc[i][j + 3] + b2e[n0 + tx * 8 + j + 3];
            *(float4*)(op + j) = v;
        }
    }
}

// Deterministic combine: y[b] = sum_k gate[b,k] * EO[slot(b,k)]
__global__ void combine_kernel(float* __restrict__ out) {
    const int b = blockIdx.x;
    const int o = threadIdx.x;
    const float g0 = g_gate[b * TOPK + 0], g1 = g_gate[b * TOPK + 1], g2 = g_gate[b * TOPK + 2];
    const int   s0 = g_slot[b * TOPK + 0], s1 = g_slot[b * TOPK + 1], s2 = g_slot[b * TOPK + 2];
    float y = g0 * g_eo[(size_t)s0 * OUTD + o]
            + g1 * g_eo[(size_t)s1 * OUTD + o]
            + g2 * g_eo[(size_t)s2 * OUTD + o];
    out[(size_t)b * OUTD + o] = y;
}

// ---------------- launch ----------------
extern "C" void kernel_launch(void* const* d_in, const int* in_sizes, int n_in,
                              void* d_out, int out_size) {
    const float* x  = (const float*)d_in[0];
    const float* wg = (const float*)d_in[1];
    const float* W1 = (const float*)d_in[2];
    const float* b1 = (const float*)d_in[3];
    const float* W2 = (const float*)d_in[4];
    const float* b2 = (const float*)d_in[5];
    float* out = (float*)d_out;

    zero_kernel<<<1, 32>>>();
    gate_kernel<<<BB / 8, 256>>>(x, wg);
    gemm1_kernel<<<dim3(HH / 128, BB / 128, NE), 256>>>(x, W1, b1);
    gemm2_kernel<<<dim3(OUTD / 128, BB / 128, NE), 256>>>(W2, b2);
    combine_kernel<<<BB, OUTD>>>(out);
    if (out_size > BB * OUTD)
        loss_kernel<<<1, 1>>>(out + (size_t)BB * OUTD);
}

// round 5
// speedup vs baseline: 1.8973x; 1.8973x over previous
#include <cuda_runtime.h>
#include <cuda_bf16.h>
#include <cstdint>

#define BB   8192
#define IN   1024
#define OUTD 256
#define NE   16
#define HH   512
#define TOPK 3

typedef __nv_bfloat16 bf16;

// ---------------- device scratch ----------------
__device__ int   g_count[NE];
__device__ float g_importance[NE];
__device__ int   g_rows[NE * BB];
__device__ int   g_slot[BB * TOPK];
__device__ float g_gate[BB * TOPK];

__device__ bf16  g_xhi[(size_t)BB * IN];
__device__ bf16  g_xlo[(size_t)BB * IN];
__device__ bf16  g_w1hi[(size_t)NE * HH * IN];    // [e][n][k] K-major
__device__ bf16  g_w1lo[(size_t)NE * HH * IN];
__device__ bf16  g_w2hi[(size_t)NE * OUTD * HH];  // [e][n][k] K-major
__device__ bf16  g_w2lo[(size_t)NE * OUTD * HH];
__device__ bf16  g_hhi[(size_t)NE * BB * HH];
__device__ bf16  g_hlo[(size_t)NE * BB * HH];
__device__ float g_eo [(size_t)NE * BB * OUTD];

// ---------------- helpers ----------------
__device__ __forceinline__ uint32_t smem_u32(const void* p) {
    uint32_t a;
    asm("{ .reg .u64 t; cvta.to.shared.u64 t, %1; cvt.u32.u64 %0, t; }" : "=r"(a) : "l"(p));
    return a;
}
#define SW128(o) ((o) ^ (((o) >> 3) & 0x70))

#define CP16(s, g) asm volatile("cp.async.cg.shared.global [%0], [%1], 16;" :: "r"(s), "l"(g) : "memory")
#define CP_COMMIT() asm volatile("cp.async.commit_group;" ::: "memory")
#define CP_WAIT1()  asm volatile("cp.async.wait_group 1;" ::: "memory")
#define CP_WAIT0()  asm volatile("cp.async.wait_group 0;" ::: "memory")

__device__ __forceinline__ void ldsm4(uint32_t* r, uint32_t addr) {
    asm volatile("ldmatrix.sync.aligned.m8n8.x4.shared.b16 {%0,%1,%2,%3}, [%4];"
                 : "=r"(r[0]), "=r"(r[1]), "=r"(r[2]), "=r"(r[3]) : "r"(addr));
}
__device__ __forceinline__ void mma16816(float* c, const uint32_t* a, const uint32_t* b) {
    asm volatile("mma.sync.aligned.m16n8k16.row.col.f32.bf16.bf16.f32 "
                 "{%0,%1,%2,%3}, {%4,%5,%6,%7}, {%8,%9}, {%0,%1,%2,%3};"
                 : "+f"(c[0]), "+f"(c[1]), "+f"(c[2]), "+f"(c[3])
                 : "r"(a[0]), "r"(a[1]), "r"(a[2]), "r"(a[3]), "r"(b[0]), "r"(b[1]));
}

__device__ __forceinline__ void split2(float v, bf16& h, bf16& l) {
    h = __float2bfloat16(v);
    l = __float2bfloat16(v - __bfloat162float(h));
}
__device__ __forceinline__ uint32_t packb(bf16 a, bf16 b) {
    return (uint32_t)__bfloat16_as_ushort(a) | ((uint32_t)__bfloat16_as_ushort(b) << 16);
}

// smem stage layout (bytes): 4 buffers of [128 rows][128B]
#define OFF_AHI 0
#define OFF_ALO 16384
#define OFF_BHI 32768
#define OFF_BLO 49152
#define STAGE   65536
#define DSMEM_SZ (2 * STAGE + 1024)

// ---------------- small kernels ----------------
__global__ void zero_kernel() {
    int t = threadIdx.x;
    if (t < NE) { g_count[t] = 0; g_importance[t] = 0.f; }
}

__global__ void gate_kernel(const float* __restrict__ x, const float* __restrict__ wg) {
    const int warp = threadIdx.x >> 5;
    const int lane = threadIdx.x & 31;
    const int row  = blockIdx.x * 8 + warp;
    const float* xr = x + (size_t)row * IN;
    float acc[NE];
#pragma unroll
    for (int e = 0; e < NE; e++) acc[e] = 0.f;
    for (int i = lane; i < IN; i += 32) {
        float xv = __ldg(xr + i);
        const float* wr = wg + i * NE;
#pragma unroll
        for (int e = 0; e < NE; e++) acc[e] += xv * __ldg(wr + e);
    }
#pragma unroll
    for (int e = 0; e < NE; e++) {
#pragma unroll
        for (int off = 16; off > 0; off >>= 1)
            acc[e] += __shfl_xor_sync(0xffffffffu, acc[e], off);
    }
    if (lane == 0) {
        float l[TOPK]; int ix[TOPK];
#pragma unroll
        for (int k = 0; k < TOPK; k++) {
            float best = -1e30f; int bi = 0;
#pragma unroll
            for (int e = 0; e < NE; e++)
                if (acc[e] > best) { best = acc[e]; bi = e; }
            l[k] = best; ix[k] = bi; acc[bi] = -1e30f;
        }
        float g[TOPK]; float s = 0.f;
#pragma unroll
        for (int k = 0; k < TOPK; k++) { g[k] = expf(l[k] - l[0]); s += g[k]; }
        float inv = 1.f / s;
#pragma unroll
        for (int k = 0; k < TOPK; k++) {
            float gk = g[k] * inv;
            int e = ix[k];
            int pos = atomicAdd(&g_count[e], 1);
            g_rows[e * BB + pos]   = row;
            g_slot[row * TOPK + k] = e * BB + pos;
            g_gate[row * TOPK + k] = gk;
            atomicAdd(&g_importance[e], gk);
        }
    }
}

__global__ void loss_kernel(float* __restrict__ out) {
    float imp[NE], ld[NE];
    float si = 0.f, sl = 0.f;
    for (int e = 0; e < NE; e++) {
        imp[e] = g_importance[e]; ld[e] = (float)g_count[e];
        si += imp[e]; sl += ld[e];
    }
    float mi = si / NE, ml = sl / NE;
    float vi = 0.f, vl = 0.f;
    for (int e = 0; e < NE; e++) {
        float di = imp[e] - mi; vi += di * di;
        float dl = ld[e]  - ml; vl += dl * dl;
    }
    vi /= (NE - 1); vl /= (NE - 1);
    out[0] = vi / (mi * mi + 1e-10f) + vl / (ml * ml + 1e-10f);
}

__global__ void convx_kernel(const float* __restrict__ x) {
    size_t i = ((size_t)blockIdx.x * 256 + threadIdx.x) * 4;
    float4 v = __ldg((const float4*)(x + i));
    bf16 h0, l0, h1, l1, h2, l2, h3, l3;
    split2(v.x, h0, l0); split2(v.y, h1, l1);
    split2(v.z, h2, l2); split2(v.w, h3, l3);
    *(uint2*)(g_xhi + i) = make_uint2(packb(h0, h1), packb(h2, h3));
    *(uint2*)(g_xlo + i) = make_uint2(packb(l0, l1), packb(l2, l3));
}

// transpose-convert: in [e][K][N] fp32 -> out [e][N][K] bf16 hi/lo
__global__ void transconv_kernel(const float* __restrict__ in, int which, int K, int N) {
    __shared__ float t[32][33];
    const float* src = in + (size_t)blockIdx.z * K * N;
    bf16* oh = (which ? g_w2hi : g_w1hi) + (size_t)blockIdx.z * N * K;
    bf16* ol = (which ? g_w2lo : g_w1lo) + (size_t)blockIdx.z * N * K;
    int k0 = blockIdx.y * 32, n0 = blockIdx.x * 32;
    int tx = threadIdx.x, ty = threadIdx.y;
    for (int r = ty; r < 32; r += 8)
        t[r][tx] = src[(size_t)(k0 + r) * N + n0 + tx];
    __syncthreads();
    for (int r = ty; r < 32; r += 8) {
        float v = t[tx][r];
        bf16 h, l; split2(v, h, l);
        oh[(size_t)(n0 + r) * K + k0 + tx] = h;
        ol[(size_t)(n0 + r) * K + k0 + tx] = l;
    }
}

// ---------------- shared GEMM core pieces ----------------
// Warp layout: 8 warps, warp_m = wid>>2 (2), warp_n = wid&3 (4); warp tile 64Mx32N.
// K chunk = 64 bf16 (128B rows, SW128).

struct Frag { float c[4][4][4]; };   // [mt][nt][reg]

__device__ __forceinline__ void compute_chunk(uint32_t sb, int mbase, int nbase, int lane,
                                              float c[4][4][4]) {
#pragma unroll
    for (int k16 = 0; k16 < 4; k16++) {
        const uint32_t kb = k16 * 32;
        // fragment addresses
        uint32_t a_addr = SW128((uint32_t)((mbase + (lane & 15)) * 128 + kb + (lane >> 4) * 16));
        uint32_t b_row  = nbase + ((lane >> 4) & 1) * 8 + (lane & 7);
        uint32_t b_k    = ((lane >> 3) & 1) * 16;

        uint32_t a[4][4], b_hi[2][4], b_lo[2][4];
#pragma unroll
        for (int mt = 0; mt < 4; mt++)
            ldsm4(a[mt], sb + OFF_AHI + SW128((uint32_t)((mbase + mt * 16 + (lane & 15)) * 128 + kb + (lane >> 4) * 16)));
#pragma unroll
        for (int bt = 0; bt < 2; bt++) {
            uint32_t ba = SW128((uint32_t)((b_row + bt * 16) * 128 + kb + b_k));
            ldsm4(b_hi[bt], sb + OFF_BHI + ba);
            ldsm4(b_lo[bt], sb + OFF_BLO + ba);
        }
        // pass 1+2: Ah*Bh, Ah*Bl
#pragma unroll
        for (int mt = 0; mt < 4; mt++)
#pragma unroll
            for (int nt = 0; nt < 4; nt++) {
                mma16816(c[mt][nt], a[mt], &b_hi[nt >> 1][(nt & 1) * 2]);
                mma16816(c[mt][nt], a[mt], &b_lo[nt >> 1][(nt & 1) * 2]);
            }
        // pass 3: Al*Bh (overwrite a with Al)
#pragma unroll
        for (int mt = 0; mt < 4; mt++)
            ldsm4(a[mt], sb + OFF_ALO + SW128((uint32_t)((mbase + mt * 16 + (lane & 15)) * 128 + kb + (lane >> 4) * 16)));
#pragma unroll
        for (int mt = 0; mt < 4; mt++)
#pragma unroll
            for (int nt = 0; nt < 4; nt++)
                mma16816(c[mt][nt], a[mt], &b_hi[nt >> 1][(nt & 1) * 2]);
    }
}

// ---------------- GEMM1: g_h = relu(x_gathered @ W1^T + b1), split-bf16 out ----------------
__global__ __launch_bounds__(256, 1) void gemm1_kernel(const float* __restrict__ b1) {
    const int e  = blockIdx.z;
    const int ne = g_count[e];
    const int m0 = blockIdx.y * 128;
    if (m0 >= ne) return;
    const int n0 = blockIdx.x * 128;
    const int tid = threadIdx.x;
    const int lane = tid & 31;
    const int wid  = tid >> 5;
    const int NC = IN / 64;

    extern __shared__ char dsm[];
    uint32_t sbase = (smem_u32(dsm) + 1023) & ~1023u;

    const int* rows = g_rows + e * BB;
    const char* Ah = (const char*)g_xhi;
    const char* Al = (const char*)g_xlo;
    const char* Bh = (const char*)(g_w1hi + (size_t)e * HH * IN);
    const char* Bl = (const char*)(g_w1lo + (size_t)e * HH * IN);

    size_t aoff[4], boff[4]; uint32_t swo[4];
#pragma unroll
    for (int j = 0; j < 4; j++) {
        int i = tid + j * 256, row = i >> 3, q = i & 7;
        int mm = m0 + row; if (mm > ne - 1) mm = ne - 1;
        aoff[j] = ((size_t)rows[mm] * IN + q * 8) * 2;
        boff[j] = ((size_t)(n0 + row) * IN + q * 8) * 2;
        swo[j]  = SW128((uint32_t)(row * 128 + q * 16));
    }

    auto load_chunk = [&](int c, int s) {
        uint32_t sb = sbase + s * STAGE;
        size_t kb = (size_t)c * 128;
#pragma unroll
        for (int j = 0; j < 4; j++) {
            CP16(sb + OFF_AHI + swo[j], Ah + aoff[j] + kb);
            CP16(sb + OFF_ALO + swo[j], Al + aoff[j] + kb);
            CP16(sb + OFF_BHI + swo[j], Bh + boff[j] + kb);
            CP16(sb + OFF_BLO + swo[j], Bl + boff[j] + kb);
        }
        CP_COMMIT();
    };

    float c[4][4][4];
#pragma unroll
    for (int mt = 0; mt < 4; mt++)
#pragma unroll
        for (int nt = 0; nt < 4; nt++)
#pragma unroll
            for (int r = 0; r < 4; r++) c[mt][nt][r] = 0.f;

    const int mbase = (wid >> 2) * 64;
    const int nbase = (wid & 3) * 32;

    load_chunk(0, 0);
    for (int cc = 0; cc < NC; cc++) {
        if (cc + 1 < NC) { load_chunk(cc + 1, (cc + 1) & 1); CP_WAIT1(); }
        else             { CP_WAIT0(); }
        __syncthreads();
        compute_chunk(sbase + (cc & 1) * STAGE, mbase, nbase, lane, c);
        __syncthreads();
    }

    // epilogue: bias + relu + hi/lo split
    const float* bbias = b1 + e * HH + n0;
#pragma unroll
    for (int mt = 0; mt < 4; mt++) {
        int r0 = mbase + mt * 16 + (lane >> 2);
#pragma unroll
        for (int nt = 0; nt < 4; nt++) {
            int col = nbase + nt * 8 + (lane & 3) * 2;
            float bv0 = __ldg(bbias + col), bv1 = __ldg(bbias + col + 1);
#pragma unroll
            for (int h = 0; h < 2; h++) {
                int m = m0 + r0 + h * 8;
                float v0 = fmaxf(c[mt][nt][2 * h + 0] + bv0, 0.f);
                float v1 = fmaxf(c[mt][nt][2 * h + 1] + bv1, 0.f);
                bf16 h0, l0, h1, l1; split2(v0, h0, l0); split2(v1, h1, l1);
                size_t idx = (size_t)(e * BB + m) * HH + n0 + col;
                *(uint32_t*)(g_hhi + idx) = packb(h0, h1);
                *(uint32_t*)(g_hlo + idx) = packb(l0, l1);
            }
        }
    }
}

// ---------------- GEMM2: g_eo = g_h @ W2^T + b2 ----------------
__global__ __launch_bounds__(256, 1) void gemm2_kernel(const float* __restrict__ b2) {
    const int e  = blockIdx.z;
    const int ne = g_count[e];
    const int m0 = blockIdx.y * 128;
    if (m0 >= ne) return;
    const int n0 = blockIdx.x * 128;
    const int tid = threadIdx.x;
    const int lane = tid & 31;
    const int wid  = tid >> 5;
    const int NC = HH / 64;

    extern __shared__ char dsm[];
    uint32_t sbase = (smem_u32(dsm) + 1023) & ~1023u;

    const char* Ah = (const char*)(g_hhi + (size_t)(e * BB) * HH);
    const char* Al = (const char*)(g_hlo + (size_t)(e * BB) * HH);
    const char* Bh = (const char*)(g_w2hi + (size_t)e * OUTD * HH);
    const char* Bl = (const char*)(g_w2lo + (size_t)e * OUTD * HH);

    size_t aoff[4], boff[4]; uint32_t swo[4];
#pragma unroll
    for (int j = 0; j < 4; j++) {
        int i = tid + j * 256, row = i >> 3, q = i & 7;
        aoff[j] = ((size_t)(m0 + row) * HH + q * 8) * 2;
        boff[j] = ((size_t)(n0 + row) * HH + q * 8) * 2;
        swo[j]  = SW128((uint32_t)(row * 128 + q * 16));
    }

    auto load_chunk = [&](int c, int s) {
        uint32_t sb = sbase + s * STAGE;
        size_t kb = (size_t)c * 128;
#pragma unroll
        for (int j = 0; j < 4; j++) {
            CP16(sb + OFF_AHI + swo[j], Ah + aoff[j] + kb);
            CP16(sb + OFF_ALO + swo[j], Al + aoff[j] + kb);
            CP16(sb + OFF_BHI + swo[j], Bh + boff[j] + kb);
            CP16(sb + OFF_BLO + swo[j], Bl + boff[j] + kb);
        }
        CP_COMMIT();
    };

    float c[4][4][4];
#pragma unroll
    for (int mt = 0; mt < 4; mt++)
#pragma unroll
        for (int nt = 0; nt < 4; nt++)
#pragma unroll
            for (int r = 0; r < 4; r++) c[mt][nt][r] = 0.f;

    const int mbase = (wid >> 2) * 64;
    const int nbase = (wid & 3) * 32;

    load_chunk(0, 0);
    for (int cc = 0; cc < NC; cc++) {
        if (cc + 1 < NC) { load_chunk(cc + 1, (cc + 1) & 1); CP_WAIT1(); }
        else             { CP_WAIT0(); }
        __syncthreads();
        compute_chunk(sbase + (cc & 1) * STAGE, mbase, nbase, lane, c);
        __syncthreads();
    }

    const float* bbias = b2 + e * OUTD + n0;
#pragma unroll
    for (int mt = 0; mt < 4; mt++) {
        int r0 = mbase + mt * 16 + (lane >> 2);
#pragma unroll
        for (int nt = 0; nt < 4; nt++) {
            int col = nbase + nt * 8 + (lane & 3) * 2;
            float bv0 = __ldg(bbias + col), bv1 = __ldg(bbias + col + 1);
#pragma unroll
            for (int h = 0; h < 2; h++) {
                int m = m0 + r0 + h * 8;
                float2 v;
                v.x = c[mt][nt][2 * h + 0] + bv0;
                v.y = c[mt][nt][2 * h + 1] + bv1;
                *(float2*)(g_eo + (size_t)(e * BB + m) * OUTD + n0 + col) = v;
            }
        }
    }
}

// ---------------- combine ----------------
__global__ void combine_kernel(float* __restrict__ out) {
    const int b = blockIdx.x;
    const int o = threadIdx.x * 4;
    const float g0 = g_gate[b * TOPK + 0], g1 = g_gate[b * TOPK + 1], g2 = g_gate[b * TOPK + 2];
    const int   s0 = g_slot[b * TOPK + 0], s1 = g_slot[b * TOPK + 1], s2 = g_slot[b * TOPK + 2];
    float4 a0 = __ldg((const float4*)(g_eo + (size_t)s0 * OUTD + o));
    float4 a1 = __ldg((const float4*)(g_eo + (size_t)s1 * OUTD + o));
    float4 a2 = __ldg((const float4*)(g_eo + (size_t)s2 * OUTD + o));
    float4 y;
    y.x = g0 * a0.x + g1 * a1.x + g2 * a2.x;
    y.y = g0 * a0.y + g1 * a1.y + g2 * a2.y;
    y.z = g0 * a0.z + g1 * a1.z + g2 * a2.z;
    y.w = g0 * a0.w + g1 * a1.w + g2 * a2.w;
    *(float4*)(out + (size_t)b * OUTD + o) = y;
}

// ---------------- launch ----------------
extern "C" void kernel_launch(void* const* d_in, const int* in_sizes, int n_in,
                              void* d_out, int out_size) {
    const float* x  = (const float*)d_in[0];
    const float* wg = (const float*)d_in[1];
    const float* W1 = (const float*)d_in[2];
    const float* b1 = (const float*)d_in[3];
    const float* W2 = (const float*)d_in[4];
    const float* b2 = (const float*)d_in[5];
    float* out = (float*)d_out;

    static int configured = 0;
    if (!configured) {
        cudaFuncSetAttribute(gemm1_kernel, cudaFuncAttributeMaxDynamicSharedMemorySize, DSMEM_SZ);
        cudaFuncSetAttribute(gemm2_kernel, cudaFuncAttributeMaxDynamicSharedMemorySize, DSMEM_SZ);
        configured = 1;
    }

    zero_kernel<<<1, 32>>>();
    gate_kernel<<<BB / 8, 256>>>(x, wg);
    convx_kernel<<<(BB * IN) / 4 / 256, 256>>>(x);
    transconv_kernel<<<dim3(HH / 32, IN / 32, NE), dim3(32, 8)>>>(W1, 0, IN, HH);
    transconv_kernel<<<dim3(OUTD / 32, HH / 32, NE), dim3(32, 8)>>>(W2, 1, HH, OUTD);
    gemm1_kernel<<<dim3(HH / 128, BB / 128, NE), 256, DSMEM_SZ>>>(b1);
    gemm2_kernel<<<dim3(OUTD / 128, BB / 128, NE), 256, DSMEM_SZ>>>(b2);
    combine_kernel<<<BB, OUTD / 4>>>(out);
    if (out_size > BB * OUTD)
        loss_kernel<<<1, 1>>>(out + (size_t)BB * OUTD);
}